// round 11
// baseline (speedup 1.0000x reference)
#include <cuda_runtime.h>
#include <cstddef>
#include <cstdint>

// Problem constants: B=2, S=512, H=256, A=128
#define BB 2
#define SS 512
#define HH 256
#define AA 128
#define HCH 8          // h-columns per a-scan unit
#define XPAD 516       // smem row pitch for scan transpose

#define GRID_N 128     // MUST be <= SM count (all blocks co-resident)

// dynamic smem: xsT (2048 floats) + staging (16 warps * 1024 floats) = 72KB
#define KS_SMEM_FLOATS (2048 + 16 * 1024)
#define KS_SMEM_BYTES  (KS_SMEM_FLOATS * 4)

// Scratch (device globals; no allocs allowed)
__device__ float g_s[BB * SS];          // raw scores s[b,j]
__device__ float g_w[BB * SS];          // e_j * am_j
__device__ float g_scale[BB * SS];      // am_i / C_i
__device__ int   g_cnt;                 // arrival counter (reset each run)
__device__ int   g_flag;                // monotonic epoch (never reset)

// ---------------------------------------------------------------------------
// ONE persistent kernel, grid 128 x 512 threads.
// Phase 1: scores (R9 structure; per-warp cp.async 4-slot ring, dist 3).
// Sync:    fence -> counter; last block runs softmax scan; epoch flag.
// Phase 2: every block writes 8 d rows; blocks 0..63 also run one a-scan unit.
// ---------------------------------------------------------------------------
__global__ __launch_bounds__(512) void k_all(
    const float* __restrict__ x, const float* __restrict__ w_a,
    const float* __restrict__ query, const int* __restrict__ amask,
    float* __restrict__ d_out, float* __restrict__ a_out)
{
    extern __shared__ float pool[];      // 72KB
    __shared__ float part[16][2];
    __shared__ float wmax[16], wsum[16];
    __shared__ int   sh_last, sh_epoch;

    float* xsT = pool;                                   // [h*8 + r]
    float* stg = pool + 2048;                            // wid*1024 + slot*256
    unsigned long long* sredU =
        reinterpret_cast<unsigned long long*>(pool + 2048);

    const int tid  = threadIdx.x;
    const int lane = tid & 31;
    const int wid  = tid >> 5;
    const int hr   = wid >> 1;            // h-range 0..7 (32 h each)
    const int ch   = wid & 1;             // col-half 0/1 (64 cols)
    const int h0   = hr * 32;
    const int r0   = blockIdx.x * 8;

    // read epoch BEFORE announcing arrival (so flag bump can't precede it)
    if (tid == 0) sh_epoch = atomicAdd(&g_flag, 0);

    // ======================= PHASE 1: scores =======================
    const float* wsrc = w_a + (size_t)(h0 + (lane >> 3)) * AA
                            + ch * 64 + (lane & 7) * 8;
    const uint32_t wdst =
        (uint32_t)__cvta_generic_to_shared(stg + wid * 1024 + lane * 8);

#define ISSUE(c)                                                             \
    asm volatile(                                                            \
        "cp.async.cg.shared.global [%0], [%1], 16;\n\t"                      \
        "cp.async.cg.shared.global [%2], [%3], 16;\n\t"                      \
        "cp.async.commit_group;"                                             \
        :: "r"(wdst + (uint32_t)(((c) & 3) * 1024)),                         \
           "l"(wsrc + (size_t)(c) * 4 * AA),                                 \
           "r"(wdst + (uint32_t)(((c) & 3) * 1024 + 16)),                    \
           "l"(wsrc + (size_t)(c) * 4 * AA + 4) : "memory")

    ISSUE(0); ISSUE(1); ISSUE(2); ISSUE(3);

    // stage 8 rows of x transposed: xsT[h*8 + r]
    {
        const int r  = tid & 7;
        const int h4 = tid >> 3;           // 0..63
        const float4 v =
            reinterpret_cast<const float4*>(x + (size_t)r0 * HH)[r * 64 + h4];
        xsT[(h4 * 4 + 0) * 8 + r] = v.x;
        xsT[(h4 * 4 + 1) * 8 + r] = v.y;
        xsT[(h4 * 4 + 2) * 8 + r] = v.z;
        xsT[(h4 * 4 + 3) * 8 + r] = v.w;
    }
    __syncthreads();

    unsigned long long acc00=0,acc01=0,acc02=0,acc03=0;
    unsigned long long acc10=0,acc11=0,acc12=0,acc13=0;

#define COMPUTE(c)                                                           \
    do {                                                                     \
        const float* wb = stg + wid * 1024 + ((c) & 3) * 256;                \
        _Pragma("unroll")                                                    \
        for (int hl = 0; hl < 4; ++hl) {                                     \
            const float2 w2 =                                                \
                *reinterpret_cast<const float2*>(wb + hl * 64 + lane * 2);   \
            unsigned long long wd0, wd1;                                     \
            asm("mov.b64 %0, {%1, %1};" : "=l"(wd0) : "f"(w2.x));            \
            asm("mov.b64 %0, {%1, %1};" : "=l"(wd1) : "f"(w2.y));            \
            const ulonglong2* xr2 =                                          \
                reinterpret_cast<const ulonglong2*>(                         \
                    xsT + (h0 + (c) * 4 + hl) * 8);                          \
            const ulonglong2 xA = xr2[0];   /* rows 0..3 (LDS.128) */        \
            const ulonglong2 xB = xr2[1];   /* rows 4..7 (LDS.128) */        \
            asm("fma.rn.f32x2 %0, %1, %2, %0;" : "+l"(acc00) : "l"(xA.x), "l"(wd0)); \
            asm("fma.rn.f32x2 %0, %1, %2, %0;" : "+l"(acc01) : "l"(xA.y), "l"(wd0)); \
            asm("fma.rn.f32x2 %0, %1, %2, %0;" : "+l"(acc02) : "l"(xB.x), "l"(wd0)); \
            asm("fma.rn.f32x2 %0, %1, %2, %0;" : "+l"(acc03) : "l"(xB.y), "l"(wd0)); \
            asm("fma.rn.f32x2 %0, %1, %2, %0;" : "+l"(acc10) : "l"(xA.x), "l"(wd1)); \
            asm("fma.rn.f32x2 %0, %1, %2, %0;" : "+l"(acc11) : "l"(xA.y), "l"(wd1)); \
            asm("fma.rn.f32x2 %0, %1, %2, %0;" : "+l"(acc12) : "l"(xB.x), "l"(wd1)); \
            asm("fma.rn.f32x2 %0, %1, %2, %0;" : "+l"(acc13) : "l"(xB.y), "l"(wd1)); \
        }                                                                    \
    } while (0)

#define WAITW(n) asm volatile("cp.async.wait_group " #n ";" ::: "memory"); __syncwarp()

    WAITW(3); COMPUTE(0); ISSUE(4);
    WAITW(3); COMPUTE(1); ISSUE(5);
    WAITW(3); COMPUTE(2); ISSUE(6);
    WAITW(3); COMPUTE(3); ISSUE(7);
    WAITW(3); COMPUTE(4);
    WAITW(2); COMPUTE(5);
    WAITW(1); COMPUTE(6);
    WAITW(0); COMPUTE(7);
#undef ISSUE
#undef COMPUTE
#undef WAITW

    __syncthreads();                       // staging free

    {
        const int c0 = ch * 64 + lane * 2;
        unsigned long long a0[4] = {acc00, acc01, acc02, acc03};
        unsigned long long a1[4] = {acc10, acc11, acc12, acc13};
#pragma unroll
        for (int rp = 0; rp < 4; ++rp) {
            sredU[(hr * 4 + rp) * 128 + c0]     = a0[rp];
            sredU[(hr * 4 + rp) * 128 + c0 + 1] = a1[rp];
        }
    }
    __syncthreads();

    {
        const int rp  = tid >> 7;
        const int col = tid & 127;
        float v0 = 0.f, v1 = 0.f;
#pragma unroll
        for (int hg = 0; hg < 8; ++hg) {
            float lo, hi;
            asm("mov.b64 {%0, %1}, %2;" : "=f"(lo), "=f"(hi)
                : "l"(sredU[(hg * 4 + rp) * 128 + col]));
            v0 += lo; v1 += hi;
        }
        const float qv = query[col];
        float slo = qv * tanhf(v0);
        float shi = qv * tanhf(v1);
#pragma unroll
        for (int o = 16; o > 0; o >>= 1) {
            slo += __shfl_down_sync(0xffffffffu, slo, o);
            shi += __shfl_down_sync(0xffffffffu, shi, o);
        }
        if (lane == 0) { part[wid][0] = slo; part[wid][1] = shi; }
    }
    __syncthreads();
    if (tid < 8) {
        const int w0  = (tid >> 1) * 4;
        const int sel = tid & 1;
        g_s[r0 + tid] = part[w0][sel] + part[w0 + 1][sel]
                      + part[w0 + 2][sel] + part[w0 + 3][sel];
    }

    // ================== GLOBAL SYNC (counter + epoch flag) ==================
    __threadfence();                       // every thread: publish its writes
    __syncthreads();
    if (tid == 0) {
        const int r = atomicAdd(&g_cnt, 1);
        sh_last = (r == GRID_N - 1);
    }
    __syncthreads();

    if (sh_last) {
        __threadfence();                   // acquire: see all blocks' g_s
        // softmax scan for both batches (512 threads each pass)
#pragma unroll
        for (int b2 = 0; b2 < BB; ++b2) {
            const float sv = g_s[b2 * SS + tid];
            float m = sv;
#pragma unroll
            for (int o = 16; o > 0; o >>= 1)
                m = fmaxf(m, __shfl_xor_sync(0xffffffffu, m, o));
            if (lane == 0) wmax[wid] = m;
            __syncthreads();
            float M = wmax[0];
#pragma unroll
            for (int k = 1; k < 16; ++k) M = fmaxf(M, wmax[k]);

            const float e = expf(sv - M);
            float sc = e;
#pragma unroll
            for (int o = 1; o < 32; o <<= 1) {
                const float t = __shfl_up_sync(0xffffffffu, sc, o);
                if (lane >= o) sc += t;
            }
            if (lane == 31) wsum[wid] = sc;
            __syncthreads();
            float off = 0.f;
#pragma unroll
            for (int k = 0; k < 16; ++k)
                if (k < wid) off += wsum[k];

            const float C  = sc + off;
            const int   am = amask[b2 * SS + tid];
            g_w[b2 * SS + tid]     = am ? e : 0.f;
            g_scale[b2 * SS + tid] = am ? (1.f / C) : 0.f;
            __syncthreads();               // wmax/wsum reuse
        }
        __threadfence();                   // publish g_w/g_scale
        __syncthreads();
        if (tid == 0) {
            g_cnt = 0;                     // reset counter for next replay
            atomicAdd(&g_flag, 1);         // bump epoch (release)
        }
    } else {
        if (tid == 0) {
            while (atomicAdd(&g_flag, 0) == sh_epoch) { }
        }
        __syncthreads();
        __threadfence();                   // acquire g_w/g_scale
    }
    __syncthreads();                       // pool reuse safety

    // ======================= PHASE 2: outputs =======================
    const int bx = (int)blockIdx.x;

    // ---- d rows: block writes 8 rows of d[bb] ----
    {
        const int bb   = bx >> 6;                  // batch
        const int ib   = (bx & 63) * 8;            // first row i
        const int rloc = tid >> 7;                 // 0..3
        const int sl   = tid & 127;                // float4 slot (cols 4*sl..)
        const float4 w4 = reinterpret_cast<const float4*>(g_w + bb * SS)[sl];
        const int j0 = sl * 4;
        float4* drow = reinterpret_cast<float4*>(d_out + (size_t)bb * SS * SS) + sl;
#pragma unroll
        for (int pass = 0; pass < 2; ++pass) {
            const int i = ib + pass * 4 + rloc;
            const float sc = g_scale[bb * SS + i];
            float4 o;
            o.x = (j0     <= i) ? w4.x * sc : 0.f;
            o.y = (j0 + 1 <= i) ? w4.y * sc : 0.f;
            o.z = (j0 + 2 <= i) ? w4.z * sc : 0.f;
            o.w = (j0 + 3 <= i) ? w4.w * sc : 0.f;
            drow[(size_t)i * 128] = o;
        }
    }

    // ---- a-scan: blocks 0..63 each do one (batch, 8-h-chunk) unit ----
    if (bx < 64) {
        float* xt   = pool;                        // [HCH][XPAD]
        float* ws   = pool + HCH * XPAD;           // [SS]
        float* scs  = ws + SS;                     // [SS]
        float* htot = scs + SS;                    // [HCH]

        const int b2  = bx >> 5;
        const int ha0 = (bx & 31) * HCH;

        ws[tid]  = g_w[b2 * SS + tid];
        scs[tid] = g_scale[b2 * SS + tid];

        const float* xb = x + (size_t)b2 * SS * HH + ha0;
#pragma unroll
        for (int it = 0; it < HCH; ++it) {
            const int flat = it * 512 + tid;       // 0..4095
            const int j  = flat >> 3;
            const int hh = flat & 7;
            xt[hh * XPAD + j] = xb[(size_t)j * HH + hh];
        }
        __syncthreads();

        const int hh   = wid >> 1;                 // h-column 0..7
        const int half = wid & 1;                  // j-half 0/1
        const int jb   = half * 256;

        float carry = 0.f;
        float vals[8];
#pragma unroll
        for (int k = 0; k < 8; ++k) {
            const int j = jb + k * 32 + lane;
            float v = xt[hh * XPAD + j] * ws[j];
#pragma unroll
            for (int o = 1; o < 32; o <<= 1) {
                const float t = __shfl_up_sync(0xffffffffu, v, o);
                if (lane >= o) v += t;
            }
            v += carry;
            carry = __shfl_sync(0xffffffffu, v, 31);
            vals[k] = v;
        }
        if (half == 0 && lane == 31) htot[hh] = carry;
        __syncthreads();

        const float base = half ? htot[hh] : 0.f;
#pragma unroll
        for (int k = 0; k < 8; ++k) {
            const int j = jb + k * 32 + lane;
            xt[hh * XPAD + j] = (vals[k] + base) * scs[j];
        }
        __syncthreads();

        float* ab = a_out + (size_t)b2 * SS * HH + ha0;
#pragma unroll
        for (int it = 0; it < HCH; ++it) {
            const int flat = it * 512 + tid;
            const int j  = flat >> 3;
            const int h2 = flat & 7;
            ab[(size_t)j * HH + h2] = xt[h2 * XPAD + j];
        }
    }
}

// ---------------------------------------------------------------------------
extern "C" void kernel_launch(void* const* d_in, const int* in_sizes, int n_in,
                              void* d_out, int out_size)
{
    const float* x     = (const float*)d_in[0];   // (B,S,H)
    const int*   amask = (const int*)  d_in[1];   // (B,S)
    const float* w_a   = (const float*)d_in[2];   // (H,A)
    const float* query = (const float*)d_in[3];   // (A,)

    float* out   = (float*)d_out;
    float* a_out = out;                                // (B,S,H) first
    float* dd    = out + (size_t)BB * SS * HH;         // (B,S,S) second

    cudaFuncSetAttribute(k_all, cudaFuncAttributeMaxDynamicSharedMemorySize,
                         KS_SMEM_BYTES);
    k_all<<<GRID_N, 512, KS_SMEM_BYTES>>>(x, w_a, query, amask, dd, a_out);
}

// round 12
// speedup vs baseline: 1.1577x; 1.1577x over previous
#include <cuda_runtime.h>
#include <cstddef>
#include <cstdint>

// Problem constants: B=2, S=512, H=256, A=128
#define BB 2
#define SS 512
#define HH 256
#define AA 128
#define HCH 8          // h-columns per a-scan unit
#define XPAD 516       // smem row pitch for scan transpose

// k_score dynamic smem: xsT (2048 floats) + staging (16 warps * 1024 floats)
#define KS_SMEM_FLOATS (2048 + 16 * 1024)
#define KS_SMEM_BYTES  (KS_SMEM_FLOATS * 4)

// Scratch (device globals; no allocs allowed)
__device__ float g_s[BB * SS];          // raw scores s[b,j]

// ---------------------------------------------------------------------------
// Kernel 1: s[b,j] = sum_a query[a] * tanh( sum_h x[b,j,h] * w_a[h,a] )
// grid 128 (8 rows/block), block 512 (16 warps). R9 structure +
// LDS.128 x-loads. Per-warp cp.async 4-slot ring, distance 3.
// ---------------------------------------------------------------------------
__global__ __launch_bounds__(512) void k_score(
    const float* __restrict__ x, const float* __restrict__ w_a,
    const float* __restrict__ query)
{
    extern __shared__ float pool[];      // 72KB: xsT(2048) + staging(16*1024)
    __shared__ float part[16][2];
    float* xsT = pool;                                   // [h*8 + r]
    float* stg = pool + 2048;                            // wid*1024 + slot*256
    unsigned long long* sredU =
        reinterpret_cast<unsigned long long*>(pool + 2048);

    const int tid  = threadIdx.x;
    const int lane = tid & 31;
    const int wid  = tid >> 5;
    const int hr   = wid >> 1;            // h-range 0..7 (32 h each)
    const int ch   = wid & 1;             // col-half 0/1 (64 cols)
    const int h0   = hr * 32;
    const int r0   = blockIdx.x * 8;

    const float* wsrc = w_a + (size_t)(h0 + (lane >> 3)) * AA
                            + ch * 64 + (lane & 7) * 8;
    const uint32_t wdst =
        (uint32_t)__cvta_generic_to_shared(stg + wid * 1024 + lane * 8);

#define ISSUE(c)                                                             \
    asm volatile(                                                            \
        "cp.async.cg.shared.global [%0], [%1], 16;\n\t"                      \
        "cp.async.cg.shared.global [%2], [%3], 16;\n\t"                      \
        "cp.async.commit_group;"                                             \
        :: "r"(wdst + (uint32_t)(((c) & 3) * 1024)),                         \
           "l"(wsrc + (size_t)(c) * 4 * AA),                                 \
           "r"(wdst + (uint32_t)(((c) & 3) * 1024 + 16)),                    \
           "l"(wsrc + (size_t)(c) * 4 * AA + 4) : "memory")

    ISSUE(0); ISSUE(1); ISSUE(2); ISSUE(3);

    // stage 8 rows of x transposed: xsT[h*8 + r]
    {
        const int r  = tid & 7;
        const int h4 = tid >> 3;           // 0..63
        const float4 v =
            reinterpret_cast<const float4*>(x + (size_t)r0 * HH)[r * 64 + h4];
        xsT[(h4 * 4 + 0) * 8 + r] = v.x;
        xsT[(h4 * 4 + 1) * 8 + r] = v.y;
        xsT[(h4 * 4 + 2) * 8 + r] = v.z;
        xsT[(h4 * 4 + 3) * 8 + r] = v.w;
    }
    __syncthreads();

    unsigned long long acc00=0,acc01=0,acc02=0,acc03=0;
    unsigned long long acc10=0,acc11=0,acc12=0,acc13=0;

#define COMPUTE(c)                                                           \
    do {                                                                     \
        const float* wb = stg + wid * 1024 + ((c) & 3) * 256;                \
        _Pragma("unroll")                                                    \
        for (int hl = 0; hl < 4; ++hl) {                                     \
            const float2 w2 =                                                \
                *reinterpret_cast<const float2*>(wb + hl * 64 + lane * 2);   \
            unsigned long long wd0, wd1;                                     \
            asm("mov.b64 %0, {%1, %1};" : "=l"(wd0) : "f"(w2.x));            \
            asm("mov.b64 %0, {%1, %1};" : "=l"(wd1) : "f"(w2.y));            \
            const ulonglong2* xr2 =                                          \
                reinterpret_cast<const ulonglong2*>(                         \
                    xsT + (h0 + (c) * 4 + hl) * 8);                          \
            const ulonglong2 xA = xr2[0];   /* rows 0..3 (LDS.128) */        \
            const ulonglong2 xB = xr2[1];   /* rows 4..7 (LDS.128) */        \
            asm("fma.rn.f32x2 %0, %1, %2, %0;" : "+l"(acc00) : "l"(xA.x), "l"(wd0)); \
            asm("fma.rn.f32x2 %0, %1, %2, %0;" : "+l"(acc01) : "l"(xA.y), "l"(wd0)); \
            asm("fma.rn.f32x2 %0, %1, %2, %0;" : "+l"(acc02) : "l"(xB.x), "l"(wd0)); \
            asm("fma.rn.f32x2 %0, %1, %2, %0;" : "+l"(acc03) : "l"(xB.y), "l"(wd0)); \
            asm("fma.rn.f32x2 %0, %1, %2, %0;" : "+l"(acc10) : "l"(xA.x), "l"(wd1)); \
            asm("fma.rn.f32x2 %0, %1, %2, %0;" : "+l"(acc11) : "l"(xA.y), "l"(wd1)); \
            asm("fma.rn.f32x2 %0, %1, %2, %0;" : "+l"(acc12) : "l"(xB.x), "l"(wd1)); \
            asm("fma.rn.f32x2 %0, %1, %2, %0;" : "+l"(acc13) : "l"(xB.y), "l"(wd1)); \
        }                                                                    \
    } while (0)

#define WAITW(n) asm volatile("cp.async.wait_group " #n ";" ::: "memory"); __syncwarp()

    WAITW(3); COMPUTE(0); ISSUE(4);
    WAITW(3); COMPUTE(1); ISSUE(5);
    WAITW(3); COMPUTE(2); ISSUE(6);
    WAITW(3); COMPUTE(3); ISSUE(7);
    WAITW(3); COMPUTE(4);
    WAITW(2); COMPUTE(5);
    WAITW(1); COMPUTE(6);
    WAITW(0); COMPUTE(7);
#undef ISSUE
#undef COMPUTE
#undef WAITW

    __syncthreads();

    {
        const int c0 = ch * 64 + lane * 2;
        unsigned long long a0[4] = {acc00, acc01, acc02, acc03};
        unsigned long long a1[4] = {acc10, acc11, acc12, acc13};
#pragma unroll
        for (int rp = 0; rp < 4; ++rp) {
            sredU[(hr * 4 + rp) * 128 + c0]     = a0[rp];
            sredU[(hr * 4 + rp) * 128 + c0 + 1] = a1[rp];
        }
    }
    __syncthreads();

    {
        const int rp  = tid >> 7;
        const int col = tid & 127;
        float v0 = 0.f, v1 = 0.f;
#pragma unroll
        for (int hg = 0; hg < 8; ++hg) {
            float lo, hi;
            asm("mov.b64 {%0, %1}, %2;" : "=f"(lo), "=f"(hi)
                : "l"(sredU[(hg * 4 + rp) * 128 + col]));
            v0 += lo; v1 += hi;
        }
        const float qv = query[col];
        float slo = qv * tanhf(v0);
        float shi = qv * tanhf(v1);
#pragma unroll
        for (int o = 16; o > 0; o >>= 1) {
            slo += __shfl_down_sync(0xffffffffu, slo, o);
            shi += __shfl_down_sync(0xffffffffu, shi, o);
        }
        if (lane == 0) { part[wid][0] = slo; part[wid][1] = shi; }
    }
    __syncthreads();
    if (tid < 8) {
        const int w0  = (tid >> 1) * 4;
        const int sel = tid & 1;
        g_s[r0 + tid] = part[w0][sel] + part[w0 + 1][sel]
                      + part[w0 + 2][sel] + part[w0 + 3][sel];
    }
}

// ---------------------------------------------------------------------------
// Kernel 2 (post): grid (96, B), 512 threads.
// EVERY block redundantly computes the softmax scan for its batch from g_s
// (1KB, L2-broadcast) into smem -- no separate scan kernel, no tiny-grid
// serialization. Then:
//  bx < 64 : writes 8 rows of d (float4 stores).
//  bx >= 64: one a-scan unit (8 h-columns) -> a.
// ---------------------------------------------------------------------------
__global__ __launch_bounds__(512) void k_post(
    const float* __restrict__ x, const int* __restrict__ amask,
    float* __restrict__ d_out, float* __restrict__ a_out)
{
    __shared__ float xt[HCH][XPAD];
    __shared__ float wsS[SS], scsS[SS];
    __shared__ float htot[HCH];
    __shared__ float rmax[16], rsum[16];

    const int b   = blockIdx.y;
    const int bx  = blockIdx.x;
    const int tid = threadIdx.x;
    const int lane = tid & 31, wid = tid >> 5;

    // ---- redundant per-block softmax scan ----
    const float sv = g_s[b * SS + tid];
    float m = sv;
#pragma unroll
    for (int o = 16; o > 0; o >>= 1)
        m = fmaxf(m, __shfl_xor_sync(0xffffffffu, m, o));
    if (lane == 0) rmax[wid] = m;
    __syncthreads();
    float M = rmax[0];
#pragma unroll
    for (int k = 1; k < 16; ++k) M = fmaxf(M, rmax[k]);

    const float e = expf(sv - M);
    float sc = e;
#pragma unroll
    for (int o = 1; o < 32; o <<= 1) {
        const float t = __shfl_up_sync(0xffffffffu, sc, o);
        if (lane >= o) sc += t;
    }
    if (lane == 31) rsum[wid] = sc;
    __syncthreads();
    float off = 0.f;
#pragma unroll
    for (int k = 0; k < 16; ++k)
        if (k < wid) off += rsum[k];

    const float C  = sc + off;
    const int   am = amask[b * SS + tid];
    wsS[tid]  = am ? e : 0.f;
    scsS[tid] = am ? (1.f / C) : 0.f;
    __syncthreads();

    if (bx < 64) {
        // ---- d rows: 8 rows, float4 stores ----
        const int ib   = bx * 8;
        const int rloc = tid >> 7;              // 0..3
        const int sl   = tid & 127;             // float4 slot
        const float4 w4 = *reinterpret_cast<const float4*>(&wsS[sl * 4]);
        const int j0 = sl * 4;
        float4* drow = reinterpret_cast<float4*>(d_out + (size_t)b * SS * SS) + sl;
#pragma unroll
        for (int pass = 0; pass < 2; ++pass) {
            const int i = ib + pass * 4 + rloc;
            const float scr = scsS[i];
            float4 o;
            o.x = (j0     <= i) ? w4.x * scr : 0.f;
            o.y = (j0 + 1 <= i) ? w4.y * scr : 0.f;
            o.z = (j0 + 2 <= i) ? w4.z * scr : 0.f;
            o.w = (j0 + 3 <= i) ? w4.w * scr : 0.f;
            drow[(size_t)i * 128] = o;
        }
        return;
    }

    // ---- a-scan unit: 8 h-columns ----
    const int h0 = (bx - 64) * HCH;
    const float* xb = x + (size_t)b * SS * HH + h0;
#pragma unroll
    for (int it = 0; it < HCH; ++it) {
        const int flat = it * 512 + tid;        // 0..4095
        const int j  = flat >> 3;
        const int hh = flat & 7;
        xt[hh][j] = xb[(size_t)j * HH + hh];
    }
    __syncthreads();

    const int hh   = wid >> 1;                  // h-column 0..7
    const int half = wid & 1;                   // j-half 0/1
    const int jb   = half * 256;

    float carry = 0.f;
    float vals[8];
#pragma unroll
    for (int k = 0; k < 8; ++k) {
        const int j = jb + k * 32 + lane;
        float v = xt[hh][j] * wsS[j];
#pragma unroll
        for (int o = 1; o < 32; o <<= 1) {
            const float t = __shfl_up_sync(0xffffffffu, v, o);
            if (lane >= o) v += t;
        }
        v += carry;
        carry = __shfl_sync(0xffffffffu, v, 31);
        vals[k] = v;
    }
    if (half == 0 && lane == 31) htot[hh] = carry;
    __syncthreads();

    const float base = half ? htot[hh] : 0.f;
#pragma unroll
    for (int k = 0; k < 8; ++k) {
        const int j = jb + k * 32 + lane;
        xt[hh][j] = (vals[k] + base) * scsS[j];
    }
    __syncthreads();

    float* ab = a_out + (size_t)b * SS * HH + h0;
#pragma unroll
    for (int it = 0; it < HCH; ++it) {
        const int flat = it * 512 + tid;
        const int j  = flat >> 3;
        const int h2 = flat & 7;
        ab[(size_t)j * HH + h2] = xt[h2][j];
    }
}

// ---------------------------------------------------------------------------
extern "C" void kernel_launch(void* const* d_in, const int* in_sizes, int n_in,
                              void* d_out, int out_size)
{
    const float* x     = (const float*)d_in[0];   // (B,S,H)
    const int*   amask = (const int*)  d_in[1];   // (B,S)
    const float* w_a   = (const float*)d_in[2];   // (H,A)
    const float* query = (const float*)d_in[3];   // (A,)

    float* out   = (float*)d_out;
    float* a_out = out;                                // (B,S,H) first
    float* dd    = out + (size_t)BB * SS * HH;         // (B,S,S) second

    cudaFuncSetAttribute(k_score, cudaFuncAttributeMaxDynamicSharedMemorySize,
                         KS_SMEM_BYTES);
    k_score<<<(BB * SS) / 8, 512, KS_SMEM_BYTES>>>(x, w_a, query);
    k_post<<<dim3(64 + HH / HCH, BB), 512>>>(x, amask, dd, a_out);
}

// round 13
// speedup vs baseline: 1.3467x; 1.1633x over previous
#include <cuda_runtime.h>
#include <cstddef>
#include <cstdint>

// Problem constants: B=2, S=512, H=256, A=128
#define BB 2
#define SS 512
#define HH 256
#define AA 128
#define HCH 4          // h-columns per a-scan unit (64 units per batch)

// k_score dynamic smem: xsT (2048 floats) + staging (16 warps * 1024 floats)
#define KS_SMEM_FLOATS (2048 + 16 * 1024)
#define KS_SMEM_BYTES  (KS_SMEM_FLOATS * 4)

// Scratch (device globals; no allocs allowed)
__device__ float g_s[BB * SS];          // raw scores s[b,j]

// ---------------------------------------------------------------------------
// Kernel 1: s[b,j] = sum_a query[a] * tanh( sum_h x[b,j,h] * w_a[h,a] )
// grid 128 (8 rows/block), block 512 (16 warps). Per-warp cp.async 4-slot
// ring, distance 3; LDS.128 x-loads. (Proven best structure.)
// ---------------------------------------------------------------------------
__global__ __launch_bounds__(512) void k_score(
    const float* __restrict__ x, const float* __restrict__ w_a,
    const float* __restrict__ query)
{
    extern __shared__ float pool[];      // 72KB: xsT(2048) + staging(16*1024)
    __shared__ float part[16][2];
    float* xsT = pool;                                   // [h*8 + r]
    float* stg = pool + 2048;                            // wid*1024 + slot*256
    unsigned long long* sredU =
        reinterpret_cast<unsigned long long*>(pool + 2048);

    const int tid  = threadIdx.x;
    const int lane = tid & 31;
    const int wid  = tid >> 5;
    const int hr   = wid >> 1;            // h-range 0..7 (32 h each)
    const int ch   = wid & 1;             // col-half 0/1 (64 cols)
    const int h0   = hr * 32;
    const int r0   = blockIdx.x * 8;

    const float* wsrc = w_a + (size_t)(h0 + (lane >> 3)) * AA
                            + ch * 64 + (lane & 7) * 8;
    const uint32_t wdst =
        (uint32_t)__cvta_generic_to_shared(stg + wid * 1024 + lane * 8);

#define ISSUE(c)                                                             \
    asm volatile(                                                            \
        "cp.async.cg.shared.global [%0], [%1], 16;\n\t"                      \
        "cp.async.cg.shared.global [%2], [%3], 16;\n\t"                      \
        "cp.async.commit_group;"                                             \
        :: "r"(wdst + (uint32_t)(((c) & 3) * 1024)),                         \
           "l"(wsrc + (size_t)(c) * 4 * AA),                                 \
           "r"(wdst + (uint32_t)(((c) & 3) * 1024 + 16)),                    \
           "l"(wsrc + (size_t)(c) * 4 * AA + 4) : "memory")

    ISSUE(0); ISSUE(1); ISSUE(2); ISSUE(3);

    // stage 8 rows of x transposed: xsT[h*8 + r]
    {
        const int r  = tid & 7;
        const int h4 = tid >> 3;           // 0..63
        const float4 v =
            reinterpret_cast<const float4*>(x + (size_t)r0 * HH)[r * 64 + h4];
        xsT[(h4 * 4 + 0) * 8 + r] = v.x;
        xsT[(h4 * 4 + 1) * 8 + r] = v.y;
        xsT[(h4 * 4 + 2) * 8 + r] = v.z;
        xsT[(h4 * 4 + 3) * 8 + r] = v.w;
    }
    __syncthreads();

    unsigned long long acc00=0,acc01=0,acc02=0,acc03=0;
    unsigned long long acc10=0,acc11=0,acc12=0,acc13=0;

#define COMPUTE(c)                                                           \
    do {                                                                     \
        const float* wb = stg + wid * 1024 + ((c) & 3) * 256;                \
        _Pragma("unroll")                                                    \
        for (int hl = 0; hl < 4; ++hl) {                                     \
            const float2 w2 =                                                \
                *reinterpret_cast<const float2*>(wb + hl * 64 + lane * 2);   \
            unsigned long long wd0, wd1;                                     \
            asm("mov.b64 %0, {%1, %1};" : "=l"(wd0) : "f"(w2.x));            \
            asm("mov.b64 %0, {%1, %1};" : "=l"(wd1) : "f"(w2.y));            \
            const ulonglong2* xr2 =                                          \
                reinterpret_cast<const ulonglong2*>(                         \
                    xsT + (h0 + (c) * 4 + hl) * 8);                          \
            const ulonglong2 xA = xr2[0];                                    \
            const ulonglong2 xB = xr2[1];                                    \
            asm("fma.rn.f32x2 %0, %1, %2, %0;" : "+l"(acc00) : "l"(xA.x), "l"(wd0)); \
            asm("fma.rn.f32x2 %0, %1, %2, %0;" : "+l"(acc01) : "l"(xA.y), "l"(wd0)); \
            asm("fma.rn.f32x2 %0, %1, %2, %0;" : "+l"(acc02) : "l"(xB.x), "l"(wd0)); \
            asm("fma.rn.f32x2 %0, %1, %2, %0;" : "+l"(acc03) : "l"(xB.y), "l"(wd0)); \
            asm("fma.rn.f32x2 %0, %1, %2, %0;" : "+l"(acc10) : "l"(xA.x), "l"(wd1)); \
            asm("fma.rn.f32x2 %0, %1, %2, %0;" : "+l"(acc11) : "l"(xA.y), "l"(wd1)); \
            asm("fma.rn.f32x2 %0, %1, %2, %0;" : "+l"(acc12) : "l"(xB.x), "l"(wd1)); \
            asm("fma.rn.f32x2 %0, %1, %2, %0;" : "+l"(acc13) : "l"(xB.y), "l"(wd1)); \
        }                                                                    \
    } while (0)

#define WAITW(n) asm volatile("cp.async.wait_group " #n ";" ::: "memory"); __syncwarp()

    WAITW(3); COMPUTE(0); ISSUE(4);
    WAITW(3); COMPUTE(1); ISSUE(5);
    WAITW(3); COMPUTE(2); ISSUE(6);
    WAITW(3); COMPUTE(3); ISSUE(7);
    WAITW(3); COMPUTE(4);
    WAITW(2); COMPUTE(5);
    WAITW(1); COMPUTE(6);
    WAITW(0); COMPUTE(7);
#undef ISSUE
#undef COMPUTE
#undef WAITW

    __syncthreads();

    {
        const int c0 = ch * 64 + lane * 2;
        unsigned long long a0[4] = {acc00, acc01, acc02, acc03};
        unsigned long long a1[4] = {acc10, acc11, acc12, acc13};
#pragma unroll
        for (int rp = 0; rp < 4; ++rp) {
            sredU[(hr * 4 + rp) * 128 + c0]     = a0[rp];
            sredU[(hr * 4 + rp) * 128 + c0 + 1] = a1[rp];
        }
    }
    __syncthreads();

    {
        const int rp  = tid >> 7;
        const int col = tid & 127;
        float v0 = 0.f, v1 = 0.f;
#pragma unroll
        for (int hg = 0; hg < 8; ++hg) {
            float lo, hi;
            asm("mov.b64 {%0, %1}, %2;" : "=f"(lo), "=f"(hi)
                : "l"(sredU[(hg * 4 + rp) * 128 + col]));
            v0 += lo; v1 += hi;
        }
        const float qv = query[col];
        float slo = qv * tanhf(v0);
        float shi = qv * tanhf(v1);
#pragma unroll
        for (int o = 16; o > 0; o >>= 1) {
            slo += __shfl_down_sync(0xffffffffu, slo, o);
            shi += __shfl_down_sync(0xffffffffu, shi, o);
        }
        if (lane == 0) { part[wid][0] = slo; part[wid][1] = shi; }
    }
    __syncthreads();
    if (tid < 8) {
        const int w0  = (tid >> 1) * 4;
        const int sel = tid & 1;
        g_s[r0 + tid] = part[w0][sel] + part[w0 + 1][sel]
                      + part[w0 + 2][sel] + part[w0 + 3][sel];
    }
}

// ---------------------------------------------------------------------------
// Kernel 2 (post): grid (64, B), 512 threads, 128 blocks total (1 wave).
// Each block:
//   0. prefetch x[b, :, h0..h0+3] via 1 cp.async.16B/thread (hidden by scan)
//   1. redundant softmax scan of its batch (g_s is L2-hot)
//   2. 8 d-rows (one oct)
//   3. one 4-column a-scan unit (16 warps = 4 quarters x 4 cols)
// ---------------------------------------------------------------------------
__global__ __launch_bounds__(512) void k_post(
    const float* __restrict__ x, const int* __restrict__ amask,
    float* __restrict__ d_out, float* __restrict__ a_out)
{
    __shared__ float xt2[SS * HCH];         // [j][hh] row-major, 8KB
    __shared__ float wsS[SS], scsS[SS];
    __shared__ float qtot[HCH][4];
    __shared__ float rmax[16], rsum[16];

    const int b   = blockIdx.y;
    const int bx  = blockIdx.x;             // 0..63
    const int tid = threadIdx.x;
    const int lane = tid & 31, wid = tid >> 5;
    const int h0  = bx * HCH;

    // ---- 0. prefetch x tile: thread tid loads row j=tid, cols h0..h0+3 ----
    {
        const float* src = x + (size_t)b * SS * HH + (size_t)tid * HH + h0;
        const uint32_t dst =
            (uint32_t)__cvta_generic_to_shared(xt2 + tid * HCH);
        asm volatile(
            "cp.async.cg.shared.global [%0], [%1], 16;\n\t"
            "cp.async.commit_group;"
            :: "r"(dst), "l"(src) : "memory");
    }

    // ---- 1. redundant softmax scan ----
    const float sv = g_s[b * SS + tid];
    float m = sv;
#pragma unroll
    for (int o = 16; o > 0; o >>= 1)
        m = fmaxf(m, __shfl_xor_sync(0xffffffffu, m, o));
    if (lane == 0) rmax[wid] = m;
    __syncthreads();
    float M = rmax[0];
#pragma unroll
    for (int k = 1; k < 16; ++k) M = fmaxf(M, rmax[k]);

    const float e = expf(sv - M);
    float sc = e;
#pragma unroll
    for (int o = 1; o < 32; o <<= 1) {
        const float t = __shfl_up_sync(0xffffffffu, sc, o);
        if (lane >= o) sc += t;
    }
    if (lane == 31) rsum[wid] = sc;
    __syncthreads();
    float off = 0.f;
#pragma unroll
    for (int k = 0; k < 16; ++k)
        if (k < wid) off += rsum[k];

    const float C  = sc + off;
    const int   am = amask[b * SS + tid];
    wsS[tid]  = am ? e : 0.f;
    scsS[tid] = am ? (1.f / C) : 0.f;
    asm volatile("cp.async.wait_group 0;" ::: "memory");
    __syncthreads();                        // wsS/scsS/xt2 all ready

    // ---- 2. d-oct: rows bx*8 .. bx*8+7 ----
    {
        const int ib   = bx * 8;
        const int rloc = tid >> 7;          // 0..3
        const int sl   = tid & 127;         // float4 slot
        const float4 w4 = *reinterpret_cast<const float4*>(&wsS[sl * 4]);
        const int j0 = sl * 4;
        float4* drow = reinterpret_cast<float4*>(d_out + (size_t)b * SS * SS) + sl;
#pragma unroll
        for (int pass = 0; pass < 2; ++pass) {
            const int i = ib + pass * 4 + rloc;
            const float scr = scsS[i];
            float4 o;
            o.x = (j0     <= i) ? w4.x * scr : 0.f;
            o.y = (j0 + 1 <= i) ? w4.y * scr : 0.f;
            o.z = (j0 + 2 <= i) ? w4.z * scr : 0.f;
            o.w = (j0 + 3 <= i) ? w4.w * scr : 0.f;
            drow[(size_t)i * 128] = o;
        }
    }

    // ---- 3. a-scan unit: 4 h-columns, 16 warps = (quarter q, col hh) ----
    {
        const int q  = wid >> 2;            // j-quarter 0..3 (128 j each)
        const int hh = wid & 3;             // h-column 0..3
        const int jb = q * 128;

        float carry = 0.f;
        float vals[4];
#pragma unroll
        for (int k = 0; k < 4; ++k) {
            const int j = jb + k * 32 + lane;
            float v = xt2[j * HCH + hh] * wsS[j];
#pragma unroll
            for (int o = 1; o < 32; o <<= 1) {
                const float t = __shfl_up_sync(0xffffffffu, v, o);
                if (lane >= o) v += t;
            }
            v += carry;
            carry = __shfl_sync(0xffffffffu, v, 31);
            vals[k] = v;
        }
        if (lane == 31) qtot[hh][q] = carry;
        __syncthreads();

        float base = 0.f;
#pragma unroll
        for (int qq = 0; qq < 3; ++qq)
            base += (qq < q) ? qtot[hh][qq] : 0.f;

#pragma unroll
        for (int k = 0; k < 4; ++k) {
            const int j = jb + k * 32 + lane;
            xt2[j * HCH + hh] = (vals[k] + base) * scsS[j];
        }
        __syncthreads();

        // writeback: thread tid writes row j=tid (float4, 16B)
        float* ab = a_out + (size_t)b * SS * HH + (size_t)tid * HH + h0;
        *reinterpret_cast<float4*>(ab) =
            *reinterpret_cast<const float4*>(xt2 + tid * HCH);
    }
}

// ---------------------------------------------------------------------------
extern "C" void kernel_launch(void* const* d_in, const int* in_sizes, int n_in,
                              void* d_out, int out_size)
{
    const float* x     = (const float*)d_in[0];   // (B,S,H)
    const int*   amask = (const int*)  d_in[1];   // (B,S)
    const float* w_a   = (const float*)d_in[2];   // (H,A)
    const float* query = (const float*)d_in[3];   // (A,)

    float* out   = (float*)d_out;
    float* a_out = out;                                // (B,S,H) first
    float* dd    = out + (size_t)BB * SS * HH;         // (B,S,S) second

    cudaFuncSetAttribute(k_score, cudaFuncAttributeMaxDynamicSharedMemorySize,
                         KS_SMEM_BYTES);
    k_score<<<(BB * SS) / 8, 512, KS_SMEM_BYTES>>>(x, w_a, query);
    k_post<<<dim3(HH / HCH, BB), 512>>>(x, amask, dd, a_out);
}